// round 1
// baseline (speedup 1.0000x reference)
#include <cuda_runtime.h>

// ---------------------------------------------------------------------------
// AttentionWithCAE: y = proj( attn( x@qkv_w.T + [q_bias,0,v_bias] ) )
// B=8, N=1024, C=768, H=12, hd=64, SCALE=0.125
// ---------------------------------------------------------------------------

#define DIM   768
#define NHEAD 12
#define HD    64
#define BB    8
#define NN_   1024
#define MTOT  (BB * NN_)          // 8192
#define QKSCALE 0.125f            // 64^-0.5

// scratch (device globals; allocation inside kernel_launch is forbidden)
__device__ float g_q[BB * NHEAD * NN_ * HD];     // [bh][n][d], pre-scaled
__device__ float g_k[BB * NHEAD * NN_ * HD];
__device__ float g_v[BB * NHEAD * NN_ * HD];
__device__ float g_attn[MTOT * DIM];             // [b*N+n][h*64+d]
__device__ unsigned char g_mask[BB * NN_];       // canonical: 1 = masked out

// ---------------------------------------------------------------------------
// Mask canonicalization: the reference mask is jnp bool; depending on the
// harness serialization it may arrive as uint8, int32, or float32 (0/1).
// Sniff the first 8192 bytes (always in-bounds) and normalize to uint8.
// Deterministic: same input bytes -> same classification -> same output.
// ---------------------------------------------------------------------------
__global__ void mask_canon_kernel(const unsigned char* __restrict__ raw) {
    __shared__ int s_misaligned_nonzero;   // any nonzero byte at offset %4 != 0
    __shared__ int s_not_f32;              // any int not in {0, 0x3f800000}
    __shared__ int s_saw_one_f32;          // any 0x3f800000
    if (threadIdx.x == 0) { s_misaligned_nonzero = 0; s_not_f32 = 0; s_saw_one_f32 = 0; }
    __syncthreads();

    int mis = 0, notf = 0, sawone = 0;
    const int* ri = (const int*)raw;
    for (int i = threadIdx.x; i < MTOT; i += blockDim.x) {
        if ((i & 3) != 0 && raw[i] != 0) mis = 1;
    }
    for (int i = threadIdx.x; i < MTOT / 4; i += blockDim.x) {   // first 2048 ints
        int v = ri[i];
        if (v == 0x3f800000) sawone = 1;
        else if (v != 0) notf = 1;
    }
    if (mis)    atomicOr(&s_misaligned_nonzero, 1);
    if (notf)   atomicOr(&s_not_f32, 1);
    if (sawone) atomicOr(&s_saw_one_f32, 1);
    __syncthreads();

    // classification: f32 if all sampled ints are {0,1.0f} and we saw a 1.0f.
    // else int32 if all misaligned bytes are zero. else uint8 (bool).
    int is_f32 = (!s_not_f32) && s_saw_one_f32;
    int is_i32 = (!is_f32) && (!s_misaligned_nonzero);

    for (int i = threadIdx.x; i < MTOT; i += blockDim.x) {
        unsigned char m;
        if (is_f32)       m = (((const float*)raw)[i] != 0.0f) ? 1 : 0;
        else if (is_i32)  m = (((const int*)raw)[i]   != 0)    ? 1 : 0;
        else              m = (raw[i] != 0) ? 1 : 0;
        g_mask[i] = m;
    }
}

// ---------------------------------------------------------------------------
// GEMM: C[M,N] = A[M,K] @ B[N,K]^T (+epilogue).  BM=BN=128, BK=16,
// 256 threads, 8x8 microtile. smem holds tiles transposed [k][m] (stride 132)
// so compute-side reads are conflict-free float4. Register-prefetch pipeline.
// MODE 0: out[m*N+n] = acc + bias_b[n]            (projection)
// MODE 1: scatter into g_q (+q_bias, *SCALE), g_k, g_v (+v_bias)
// ---------------------------------------------------------------------------
#define BM 128
#define BN 128
#define BK 16
#define SPAD 132

template <int MODE>
__global__ __launch_bounds__(256) void gemm_kernel(
    const float* __restrict__ A, const float* __restrict__ Bw,
    const float* __restrict__ bias_a, const float* __restrict__ bias_b,
    float* __restrict__ out, int M, int N, int K)
{
    __shared__ float As[BK][SPAD];
    __shared__ float Bs[BK][SPAD];

    const int tid = threadIdx.x;
    const int ty = tid >> 4, tx = tid & 15;
    const int m0 = blockIdx.y * BM;
    const int n0 = blockIdx.x * BN;

    const int lm = tid >> 2;          // 0..63 row within half-tile
    const int lk = (tid & 3) * 4;     // k offset {0,4,8,12}

    float4 pa[2], pb[2];
    float acc[8][8];
#pragma unroll
    for (int i = 0; i < 8; i++)
#pragma unroll
        for (int j = 0; j < 8; j++) acc[i][j] = 0.f;

    const int nk = K / BK;

    // prologue: tile 0
#pragma unroll
    for (int p = 0; p < 2; p++) {
        int m = lm + p * 64;
        pa[p] = *(const float4*)&A [(size_t)(m0 + m) * K + lk];
        pb[p] = *(const float4*)&Bw[(size_t)(n0 + m) * K + lk];
    }
#pragma unroll
    for (int p = 0; p < 2; p++) {
        int m = lm + p * 64;
        As[lk + 0][m] = pa[p].x; As[lk + 1][m] = pa[p].y;
        As[lk + 2][m] = pa[p].z; As[lk + 3][m] = pa[p].w;
        Bs[lk + 0][m] = pb[p].x; Bs[lk + 1][m] = pb[p].y;
        Bs[lk + 2][m] = pb[p].z; Bs[lk + 3][m] = pb[p].w;
    }
    __syncthreads();

    for (int kt = 0; kt < nk; kt++) {
        if (kt + 1 < nk) {
            int k0 = (kt + 1) * BK;
#pragma unroll
            for (int p = 0; p < 2; p++) {
                int m = lm + p * 64;
                pa[p] = *(const float4*)&A [(size_t)(m0 + m) * K + k0 + lk];
                pb[p] = *(const float4*)&Bw[(size_t)(n0 + m) * K + k0 + lk];
            }
        }
#pragma unroll
        for (int kk = 0; kk < BK; kk++) {
            float4 a0 = *(const float4*)&As[kk][ty * 8];
            float4 a1 = *(const float4*)&As[kk][ty * 8 + 4];
            float4 b0 = *(const float4*)&Bs[kk][tx * 8];
            float4 b1 = *(const float4*)&Bs[kk][tx * 8 + 4];
            float av[8] = {a0.x, a0.y, a0.z, a0.w, a1.x, a1.y, a1.z, a1.w};
            float bv[8] = {b0.x, b0.y, b0.z, b0.w, b1.x, b1.y, b1.z, b1.w};
#pragma unroll
            for (int i = 0; i < 8; i++)
#pragma unroll
                for (int j = 0; j < 8; j++) acc[i][j] += av[i] * bv[j];
        }
        __syncthreads();
        if (kt + 1 < nk) {
#pragma unroll
            for (int p = 0; p < 2; p++) {
                int m = lm + p * 64;
                As[lk + 0][m] = pa[p].x; As[lk + 1][m] = pa[p].y;
                As[lk + 2][m] = pa[p].z; As[lk + 3][m] = pa[p].w;
                Bs[lk + 0][m] = pb[p].x; Bs[lk + 1][m] = pb[p].y;
                Bs[lk + 2][m] = pb[p].z; Bs[lk + 3][m] = pb[p].w;
            }
            __syncthreads();
        }
    }

    // epilogue
#pragma unroll
    for (int i = 0; i < 8; i++) {
        int m = m0 + ty * 8 + i;
#pragma unroll
        for (int j = 0; j < 8; j++) {
            int n = n0 + tx * 8 + j;
            float v = acc[i][j];
            if (MODE == 0) {
                out[(size_t)m * N + n] = v + bias_b[n];
            } else {
                int which = n / DIM;         // uniform per block (768 % 128 == 0)
                int cc = n % DIM;
                int h = cc / HD, d = cc % HD;
                int b = m / NN_, nn = m % NN_;
                size_t dst = ((size_t)(b * NHEAD + h) * NN_ + nn) * HD + d;
                if (which == 0)      g_q[dst] = (v + bias_a[cc]) * QKSCALE;
                else if (which == 1) g_k[dst] = v;
                else                 g_v[dst] = v + bias_b[cc];
            }
        }
    }
}

// ---------------------------------------------------------------------------
// Flash-style attention: one block per (64 q-rows, head). 256 threads (16x16),
// 4x4 microtiles. Online softmax, k-tile = 64. P reuses the K smem buffer.
// smem: Qs[64][64] + Ks[64][65] + Vs[64][64] + maskf[64]  = 49664 B (dynamic)
// ---------------------------------------------------------------------------
#define ATTN_SMEM_FLOATS (64 * 64 + 64 * 65 + 64 * 64 + 64)
#define ATTN_SMEM_BYTES  (ATTN_SMEM_FLOATS * 4)

__device__ __forceinline__ float allred_max16(float v) {
#pragma unroll
    for (int off = 1; off < 16; off <<= 1)
        v = fmaxf(v, __shfl_xor_sync(0xffffffffu, v, off));
    return v;
}
__device__ __forceinline__ float allred_sum16(float v) {
#pragma unroll
    for (int off = 1; off < 16; off <<= 1)
        v += __shfl_xor_sync(0xffffffffu, v, off);
    return v;
}

__global__ __launch_bounds__(256) void attn_kernel() {
    extern __shared__ float sm[];
    float* Qs = sm;                       // [64][64]
    float* Ks = sm + 64 * 64;             // [64][65], reused as P
    float* Vs = Ks + 64 * 65;             // [64][64]
    float* Mf = Vs + 64 * 64;             // [64] mask flags (1 = masked)

    const int tid = threadIdx.x;
    const int ty = tid >> 4, tx = tid & 15;
    const int q0 = blockIdx.x * 64;
    const int bh = blockIdx.y;            // 0..95
    const int b  = bh / NHEAD;
    const int h  = bh % NHEAD;

    const float* qbase = g_q + (size_t)bh * NN_ * HD;
    const float* kbase = g_k + (size_t)bh * NN_ * HD;
    const float* vbase = g_v + (size_t)bh * NN_ * HD;

    // load Q tile (float4, coalesced, conflict-free stores)
    {
        int r = tid >> 2;
        int c0 = (tid & 3) * 16;
#pragma unroll
        for (int p = 0; p < 4; p++)
            *(float4*)&Qs[r * 64 + c0 + p * 4] =
                *(const float4*)&qbase[(size_t)(q0 + r) * HD + c0 + p * 4];
    }

    float o_[4][4];
    float m_i[4], l_i[4];
#pragma unroll
    for (int i = 0; i < 4; i++) {
        m_i[i] = -1e30f; l_i[i] = 0.f;
#pragma unroll
        for (int j = 0; j < 4; j++) o_[i][j] = 0.f;
    }
    __syncthreads();

    for (int kt = 0; kt < NN_ / 64; kt++) {
        const int k0 = kt * 64;
        // load K (scalar stores into padded rows) and V (float4) tiles
        {
            int r = tid >> 2;
            int c0 = (tid & 3) * 16;
#pragma unroll
            for (int p = 0; p < 4; p++) {
                float4 kv = *(const float4*)&kbase[(size_t)(k0 + r) * HD + c0 + p * 4];
                Ks[r * 65 + c0 + p * 4 + 0] = kv.x;
                Ks[r * 65 + c0 + p * 4 + 1] = kv.y;
                Ks[r * 65 + c0 + p * 4 + 2] = kv.z;
                Ks[r * 65 + c0 + p * 4 + 3] = kv.w;
                *(float4*)&Vs[r * 64 + c0 + p * 4] =
                    *(const float4*)&vbase[(size_t)(k0 + r) * HD + c0 + p * 4];
            }
            if (tid < 64) Mf[tid] = g_mask[b * NN_ + k0 + tid] ? 1.f : 0.f;
        }
        __syncthreads();

        // S = Q K^T  (4x4 per thread)
        float s[4][4] = {{0.f}};
#pragma unroll 8
        for (int d = 0; d < 64; d++) {
            float av[4], bv[4];
#pragma unroll
            for (int i = 0; i < 4; i++) av[i] = Qs[(ty * 4 + i) * 64 + d];
#pragma unroll
            for (int j = 0; j < 4; j++) bv[j] = Ks[(tx * 4 + j) * 65 + d];
#pragma unroll
            for (int i = 0; i < 4; i++)
#pragma unroll
                for (int j = 0; j < 4; j++) s[i][j] += av[i] * bv[j];
        }
        // mask
        float mf[4];
#pragma unroll
        for (int j = 0; j < 4; j++) mf[j] = Mf[tx * 4 + j];
#pragma unroll
        for (int i = 0; i < 4; i++)
#pragma unroll
            for (int j = 0; j < 4; j++)
                if (mf[j] > 0.5f) s[i][j] = -1e30f;

        // online softmax update
#pragma unroll
        for (int i = 0; i < 4; i++) {
            float mt = fmaxf(fmaxf(s[i][0], s[i][1]), fmaxf(s[i][2], s[i][3]));
            mt = allred_max16(mt);
            float mn = fmaxf(m_i[i], mt);
            float corr = __expf(m_i[i] - mn);
            float rs = 0.f;
#pragma unroll
            for (int j = 0; j < 4; j++) { s[i][j] = __expf(s[i][j] - mn); rs += s[i][j]; }
            rs = allred_sum16(rs);
            l_i[i] = l_i[i] * corr + rs;
            m_i[i] = mn;
#pragma unroll
            for (int j = 0; j < 4; j++) o_[i][j] *= corr;
        }
        __syncthreads();   // everyone done reading Ks
        // write P into Ks buffer
#pragma unroll
        for (int i = 0; i < 4; i++)
#pragma unroll
            for (int j = 0; j < 4; j++)
                Ks[(ty * 4 + i) * 65 + tx * 4 + j] = s[i][j];
        __syncthreads();

        // O += P @ V
#pragma unroll 8
        for (int c = 0; c < 64; c++) {
            float av[4], bv[4];
#pragma unroll
            for (int i = 0; i < 4; i++) av[i] = Ks[(ty * 4 + i) * 65 + c];
#pragma unroll
            for (int j = 0; j < 4; j++) bv[j] = Vs[c * 64 + tx * 4 + j];
#pragma unroll
            for (int i = 0; i < 4; i++)
#pragma unroll
                for (int j = 0; j < 4; j++) o_[i][j] += av[i] * bv[j];
        }
        __syncthreads();   // before next tile load overwrites Ks/Vs
    }

    // normalize + write to [b*N+n][h*64+d]
#pragma unroll
    for (int i = 0; i < 4; i++) {
        float inv = 1.f / l_i[i];
        int n = q0 + ty * 4 + i;
#pragma unroll
        for (int j = 0; j < 4; j++)
            g_attn[(size_t)(b * NN_ + n) * DIM + h * HD + tx * 4 + j] = o_[i][j] * inv;
    }
}

// ---------------------------------------------------------------------------
// launch
// ---------------------------------------------------------------------------
extern "C" void kernel_launch(void* const* d_in, const int* in_sizes, int n_in,
                              void* d_out, int out_size) {
    const float* x       = (const float*)d_in[0];
    const unsigned char* mask_raw = (const unsigned char*)d_in[1];
    const float* qkv_w   = (const float*)d_in[2];
    const float* q_bias  = (const float*)d_in[3];
    const float* v_bias  = (const float*)d_in[4];
    const float* proj_w  = (const float*)d_in[5];
    const float* proj_b  = (const float*)d_in[6];
    float* out           = (float*)d_out;

    (void)in_sizes; (void)n_in; (void)out_size;

    cudaFuncSetAttribute(attn_kernel,
                         cudaFuncAttributeMaxDynamicSharedMemorySize,
                         ATTN_SMEM_BYTES);

    // 1) canonicalize mask dtype
    mask_canon_kernel<<<1, 256>>>(mask_raw);

    // 2) QKV projection: [8192,768] @ [2304,768]^T -> scatter q/k/v
    gemm_kernel<1><<<dim3(3 * DIM / BN, MTOT / BM), 256>>>(
        x, qkv_w, q_bias, v_bias, nullptr, MTOT, 3 * DIM, DIM);

    // 3) attention
    attn_kernel<<<dim3(NN_ / 64, BB * NHEAD), 256, ATTN_SMEM_BYTES>>>();

    // 4) output projection: [8192,768] @ [768,768]^T + proj_b
    float* attn_ptr = nullptr;
    cudaGetSymbolAddress((void**)&attn_ptr, g_attn);
    gemm_kernel<0><<<dim3(DIM / BN, MTOT / BM), 256>>>(
        attn_ptr, proj_w, nullptr, proj_b, out, MTOT, DIM, DIM);
}

// round 3
// speedup vs baseline: 1.5025x; 1.5025x over previous
#include <cuda_runtime.h>
#include <cuda_bf16.h>
#include <cstdint>

// ---------------------------------------------------------------------------
// AttentionWithCAE: y = proj( attn( x@qkv_w.T + [q_bias,0,v_bias] ) )
// B=8, N=1024, C=768, H=12, hd=64, SCALE=0.125
// GEMMs: warp-level mma.sync bf16 (split hi/lo 3-term, fp32 accumulate).
// (tcgen05/TMA unavailable: harness compiles at sm_103 without the 'a' target)
// ---------------------------------------------------------------------------

#define DIM   768
#define NHEAD 12
#define HD    64
#define BB    8
#define NN_   1024
#define MTOT  (BB * NN_)          // 8192
#define QKSCALE 0.125f
#define K2    (3 * DIM)           // 2304 expanded K
#define NC64  (K2 / 64)           // 36 K-chunks of 64

// scratch (device globals; no allocations allowed)
__device__ float g_q[BB * NHEAD * NN_ * HD];
__device__ float g_k[BB * NHEAD * NN_ * HD];
__device__ float g_v[BB * NHEAD * NN_ * HD];
__device__ float g_attn[MTOT * DIM];
__device__ unsigned char g_mask[BB * NN_];

__device__ __nv_bfloat16 g_xs[MTOT * K2];        // x split    [Ah,Ah,Al]
__device__ __nv_bfloat16 g_ws[3 * DIM * K2];     // qkv_w split [Bh,Bl,Bh]
__device__ __nv_bfloat16 g_as[MTOT * K2];        // attn out split
__device__ __nv_bfloat16 g_ps[DIM * K2];         // proj_w split

// ---------------------------------------------------------------------------
// helpers
// ---------------------------------------------------------------------------
__device__ __forceinline__ uint32_t smem_u32(const void* p) {
    uint32_t a;
    asm("{ .reg .u64 t; cvta.to.shared.u64 t, %1; cvt.u32.u64 %0, t; }"
        : "=r"(a) : "l"(p));
    return a;
}
#define SW128(o) ((o) ^ (((o) >> 3) & 0x70))

#define CP_ASYNC16(dst, src) \
    asm volatile("cp.async.cg.shared.global [%0], [%1], 16;" \
                 :: "r"(dst), "l"(src) : "memory")
#define CP_COMMIT() asm volatile("cp.async.commit_group;" ::: "memory")
#define CP_WAIT0()  asm volatile("cp.async.wait_group 0;" ::: "memory")
#define CP_WAIT1()  asm volatile("cp.async.wait_group 1;" ::: "memory")

__device__ __forceinline__ void ldsm4(uint32_t* r, uint32_t addr) {
    asm volatile("ldmatrix.sync.aligned.m8n8.x4.shared.b16 {%0,%1,%2,%3}, [%4];"
        : "=r"(r[0]), "=r"(r[1]), "=r"(r[2]), "=r"(r[3]) : "r"(addr));
}
__device__ __forceinline__ void mma16816(float* d, const uint32_t* a,
                                         const uint32_t* b) {
    asm volatile(
        "mma.sync.aligned.m16n8k16.row.col.f32.bf16.bf16.f32 "
        "{%0,%1,%2,%3}, {%4,%5,%6,%7}, {%8,%9}, {%0,%1,%2,%3};"
        : "+f"(d[0]), "+f"(d[1]), "+f"(d[2]), "+f"(d[3])
        : "r"(a[0]), "r"(a[1]), "r"(a[2]), "r"(a[3]), "r"(b[0]), "r"(b[1]));
}

// ---------------------------------------------------------------------------
// mask canonicalization (handles bool/int32/f32 payloads)
// ---------------------------------------------------------------------------
__global__ void mask_canon_kernel(const unsigned char* __restrict__ raw) {
    __shared__ int s_mis, s_notf, s_one;
    if (threadIdx.x == 0) { s_mis = 0; s_notf = 0; s_one = 0; }
    __syncthreads();
    int mis = 0, notf = 0, one = 0;
    const int* ri = (const int*)raw;
    for (int i = threadIdx.x; i < MTOT; i += blockDim.x)
        if ((i & 3) != 0 && raw[i] != 0) mis = 1;
    for (int i = threadIdx.x; i < MTOT / 4; i += blockDim.x) {
        int v = ri[i];
        if (v == 0x3f800000) one = 1; else if (v != 0) notf = 1;
    }
    if (mis)  atomicOr(&s_mis, 1);
    if (notf) atomicOr(&s_notf, 1);
    if (one)  atomicOr(&s_one, 1);
    __syncthreads();
    int is_f32 = (!s_notf) && s_one;
    int is_i32 = (!is_f32) && (!s_mis);
    for (int i = threadIdx.x; i < MTOT; i += blockDim.x) {
        unsigned char m;
        if (is_f32)      m = (((const float*)raw)[i] != 0.0f) ? 1 : 0;
        else if (is_i32) m = (((const int*)raw)[i]   != 0)    ? 1 : 0;
        else             m = (raw[i] != 0) ? 1 : 0;
        g_mask[i] = m;
    }
}

// ---------------------------------------------------------------------------
// split conversion: src[rows][768] f32 -> dst[rows][2304] bf16
// pattern 0 (A side): [hi, hi, lo] ; pattern 1 (B side): [hi, lo, hi]
// ---------------------------------------------------------------------------
template <int PAT>
__global__ void split_kernel(const float* __restrict__ src,
                             __nv_bfloat16* __restrict__ dst, int total) {
    int i = blockIdx.x * blockDim.x + threadIdx.x;
    if (i >= total) return;
    int m = i / DIM, k = i % DIM;
    float v = src[i];
    __nv_bfloat16 h = __float2bfloat16(v);
    __nv_bfloat16 l = __float2bfloat16(v - __bfloat162float(h));
    size_t base = (size_t)m * K2 + k;
    if (PAT == 0) { dst[base] = h; dst[base + DIM] = h; dst[base + 2 * DIM] = l; }
    else          { dst[base] = h; dst[base + DIM] = l; dst[base + 2 * DIM] = h; }
}

// ---------------------------------------------------------------------------
// mma.sync GEMM: C[M, Ntot] = A'[M,2304] @ B'[Ntot,2304]^T
// 128x128 tile, BK=64 bf16 (128B rows, SW128 swizzle), cp.async 2-stage,
// 8 warps (4x2), each 32x64 via m16n8k16 bf16, fp32 accum.
// MODE 0: out = C + bias_b[n]            (projection)
// MODE 1: scatter to g_q (+q_bias,*scale) / g_k / g_v (+v_bias)
// ---------------------------------------------------------------------------
#define TILE16K  16384                 // one 128x64 bf16 tile (swizzled)
#define STAGE_B  (2 * TILE16K)         // A + B per stage
#define GEMM_DSMEM (2 * STAGE_B)       // 65536

template <int MODE>
__global__ __launch_bounds__(256, 1) void mma_gemm_kernel(
    const __nv_bfloat16* __restrict__ A2, const __nv_bfloat16* __restrict__ B2,
    const float* __restrict__ bias_a, const float* __restrict__ bias_b,
    float* __restrict__ out, int Ntot)
{
    extern __shared__ char sm[];
    const int tid  = threadIdx.x;
    const int lane = tid & 31;
    const int wid  = tid >> 5;
    const int wm   = wid & 3;          // 0..3 -> rows wm*32
    const int wn   = wid >> 2;         // 0..1 -> cols wn*64
    const int m0 = blockIdx.y * 128;
    const int n0 = blockIdx.x * 128;

    float acc[2][8][4];
#pragma unroll
    for (int a = 0; a < 2; a++)
#pragma unroll
        for (int b = 0; b < 8; b++)
#pragma unroll
            for (int c = 0; c < 4; c++) acc[a][b][c] = 0.f;

    auto load_tiles = [&](int kt, int s) {
        char* sa = sm + s * STAGE_B;
        char* sb = sa + TILE16K;
        const int k0 = kt * 64;
#pragma unroll
        for (int i = 0; i < 4; i++) {
            int idx = i * 256 + tid;           // 0..1023
            int r = idx >> 3, ch = idx & 7;
            uint32_t dst = smem_u32(sa + SW128((uint32_t)(r * 128 + ch * 16)));
            CP_ASYNC16(dst, A2 + (size_t)(m0 + r) * K2 + k0 + ch * 8);
        }
#pragma unroll
        for (int i = 0; i < 4; i++) {
            int idx = i * 256 + tid;
            int r = idx >> 3, ch = idx & 7;
            uint32_t dst = smem_u32(sb + SW128((uint32_t)(r * 128 + ch * 16)));
            CP_ASYNC16(dst, B2 + (size_t)(n0 + r) * K2 + k0 + ch * 8);
        }
    };

    load_tiles(0, 0);
    CP_COMMIT();

    for (int kt = 0; kt < NC64; kt++) {
        const int s = kt & 1;
        if (kt + 1 < NC64) {
            load_tiles(kt + 1, s ^ 1);
            CP_COMMIT();
            CP_WAIT1();
        } else {
            CP_WAIT0();
        }
        __syncthreads();

        const uint32_t a_base = smem_u32(sm + s * STAGE_B);
        const uint32_t b_base = a_base + TILE16K;
#pragma unroll
        for (int ks = 0; ks < 4; ks++) {
            uint32_t afr[2][4];
#pragma unroll
            for (int mt = 0; mt < 2; mt++) {
                int row = wm * 32 + mt * 16 + (lane & 15);
                uint32_t off = SW128((uint32_t)(row * 128 + ks * 32
                                                + ((lane >> 4) << 4)));
                ldsm4(afr[mt], a_base + off);
            }
            uint32_t bfr[4][4];
#pragma unroll
            for (int p = 0; p < 4; p++) {
                int row = wn * 64 + p * 16 + ((lane >> 4) << 3) + (lane & 7);
                uint32_t off = SW128((uint32_t)(row * 128 + ks * 32
                                                + (((lane >> 3) & 1) << 4)));
                ldsm4(bfr[p], b_base + off);
            }
#pragma unroll
            for (int mt = 0; mt < 2; mt++)
#pragma unroll
                for (int p = 0; p < 4; p++) {
                    mma16816(acc[mt][2 * p + 0], afr[mt], &bfr[p][0]);
                    mma16816(acc[mt][2 * p + 1], afr[mt], &bfr[p][2]);
                }
        }
        __syncthreads();
    }

    // epilogue straight from registers
#pragma unroll
    for (int mt = 0; mt < 2; mt++) {
#pragma unroll
        for (int nt = 0; nt < 8; nt++) {
            int rb = m0 + wm * 32 + mt * 16 + (lane >> 2);
            int cb = n0 + wn * 64 + nt * 8 + ((lane & 3) << 1);
#pragma unroll
            for (int h2 = 0; h2 < 2; h2++) {
                int m = rb + h2 * 8;
                float v0 = acc[mt][nt][h2 * 2 + 0];
                float v1 = acc[mt][nt][h2 * 2 + 1];
                if (MODE == 0) {
                    float2 o = make_float2(v0 + bias_b[cb], v1 + bias_b[cb + 1]);
                    *(float2*)&out[(size_t)m * Ntot + cb] = o;
                } else {
                    int which = cb / DIM;
                    int cc = cb - which * DIM;
                    int h = cc >> 6, d = cc & 63;
                    int b = m >> 10, nn = m & 1023;
                    size_t dst = ((size_t)(b * NHEAD + h) * NN_ + nn) * HD + d;
                    if (which == 0) {
                        float2 o = make_float2((v0 + bias_a[cc]) * QKSCALE,
                                               (v1 + bias_a[cc + 1]) * QKSCALE);
                        *(float2*)&g_q[dst] = o;
                    } else if (which == 1) {
                        *(float2*)&g_k[dst] = make_float2(v0, v1);
                    } else {
                        float2 o = make_float2(v0 + bias_b[cc],
                                               v1 + bias_b[cc + 1]);
                        *(float2*)&g_v[dst] = o;
                    }
                }
            }
        }
    }
}

// ---------------------------------------------------------------------------
// Flash-style attention (fp32 SIMT, unchanged from R1)
// ---------------------------------------------------------------------------
#define ATTN_SMEM_FLOATS (64 * 64 + 64 * 65 + 64 * 64 + 64)
#define ATTN_SMEM_BYTES  (ATTN_SMEM_FLOATS * 4)

__device__ __forceinline__ float allred_max16(float v) {
#pragma unroll
    for (int off = 1; off < 16; off <<= 1)
        v = fmaxf(v, __shfl_xor_sync(0xffffffffu, v, off));
    return v;
}
__device__ __forceinline__ float allred_sum16(float v) {
#pragma unroll
    for (int off = 1; off < 16; off <<= 1)
        v += __shfl_xor_sync(0xffffffffu, v, off);
    return v;
}

__global__ __launch_bounds__(256) void attn_kernel() {
    extern __shared__ float smf[];
    float* Qs = smf;
    float* Ks = smf + 64 * 64;
    float* Vs = Ks + 64 * 65;
    float* Mf = Vs + 64 * 64;

    const int tid = threadIdx.x;
    const int ty = tid >> 4, tx = tid & 15;
    const int q0 = blockIdx.x * 64;
    const int bh = blockIdx.y;
    const int b  = bh / NHEAD;

    const float* qbase = g_q + (size_t)bh * NN_ * HD;
    const float* kbase = g_k + (size_t)bh * NN_ * HD;
    const float* vbase = g_v + (size_t)bh * NN_ * HD;

    {
        int r = tid >> 2;
        int c0 = (tid & 3) * 16;
#pragma unroll
        for (int p = 0; p < 4; p++)
            *(float4*)&Qs[r * 64 + c0 + p * 4] =
                *(const float4*)&qbase[(size_t)(q0 + r) * HD + c0 + p * 4];
    }

    float o_[4][4];
    float m_i[4], l_i[4];
#pragma unroll
    for (int i = 0; i < 4; i++) {
        m_i[i] = -1e30f; l_i[i] = 0.f;
#pragma unroll
        for (int j = 0; j < 4; j++) o_[i][j] = 0.f;
    }
    __syncthreads();

    for (int kt = 0; kt < NN_ / 64; kt++) {
        const int k0 = kt * 64;
        {
            int r = tid >> 2;
            int c0 = (tid & 3) * 16;
#pragma unroll
            for (int p = 0; p < 4; p++) {
                float4 kv = *(const float4*)&kbase[(size_t)(k0 + r) * HD + c0 + p * 4];
                Ks[r * 65 + c0 + p * 4 + 0] = kv.x;
                Ks[r * 65 + c0 + p * 4 + 1] = kv.y;
                Ks[r * 65 + c0 + p * 4 + 2] = kv.z;
                Ks[r * 65 + c0 + p * 4 + 3] = kv.w;
                *(float4*)&Vs[r * 64 + c0 + p * 4] =
                    *(const float4*)&vbase[(size_t)(k0 + r) * HD + c0 + p * 4];
            }
            if (tid < 64) Mf[tid] = g_mask[b * NN_ + k0 + tid] ? 1.f : 0.f;
        }
        __syncthreads();

        float s[4][4] = {{0.f}};
#pragma unroll 8
        for (int d = 0; d < 64; d++) {
            float av[4], bv[4];
#pragma unroll
            for (int i = 0; i < 4; i++) av[i] = Qs[(ty * 4 + i) * 64 + d];
#pragma unroll
            for (int j = 0; j < 4; j++) bv[j] = Ks[(tx * 4 + j) * 65 + d];
#pragma unroll
            for (int i = 0; i < 4; i++)
#pragma unroll
                for (int j = 0; j < 4; j++) s[i][j] += av[i] * bv[j];
        }
        float mf[4];
#pragma unroll
        for (int j = 0; j < 4; j++) mf[j] = Mf[tx * 4 + j];
#pragma unroll
        for (int i = 0; i < 4; i++)
#pragma unroll
            for (int j = 0; j < 4; j++)
                if (mf[j] > 0.5f) s[i][j] = -1e30f;

#pragma unroll
        for (int i = 0; i < 4; i++) {
            float mt = fmaxf(fmaxf(s[i][0], s[i][1]), fmaxf(s[i][2], s[i][3]));
            mt = allred_max16(mt);
            float mn = fmaxf(m_i[i], mt);
            float corr = __expf(m_i[i] - mn);
            float rs = 0.f;
#pragma unroll
            for (int j = 0; j < 4; j++) { s[i][j] = __expf(s[i][j] - mn); rs += s[i][j]; }
            rs = allred_sum16(rs);
            l_i[i] = l_i[i] * corr + rs;
            m_i[i] = mn;
#pragma unroll
            for (int j = 0; j < 4; j++) o_[i][j] *= corr;
        }
        __syncthreads();
#pragma unroll
        for (int i = 0; i < 4; i++)
#pragma unroll
            for (int j = 0; j < 4; j++)
                Ks[(ty * 4 + i) * 65 + tx * 4 + j] = s[i][j];
        __syncthreads();

#pragma unroll 8
        for (int c = 0; c < 64; c++) {
            float av[4], bv[4];
#pragma unroll
            for (int i = 0; i < 4; i++) av[i] = Ks[(ty * 4 + i) * 65 + c];
#pragma unroll
            for (int j = 0; j < 4; j++) bv[j] = Vs[c * 64 + tx * 4 + j];
#pragma unroll
            for (int i = 0; i < 4; i++)
#pragma unroll
                for (int j = 0; j < 4; j++) o_[i][j] += av[i] * bv[j];
        }
        __syncthreads();
    }

#pragma unroll
    for (int i = 0; i < 4; i++) {
        float inv = 1.f / l_i[i];
        int n = q0 + ty * 4 + i;
#pragma unroll
        for (int j = 0; j < 4; j++)
            g_attn[(size_t)((size_t)b * NN_ + n) * DIM + (bh % NHEAD) * HD + tx * 4 + j] =
                o_[i][j] * inv;
    }
}

// ---------------------------------------------------------------------------
// launch
// ---------------------------------------------------------------------------
extern "C" void kernel_launch(void* const* d_in, const int* in_sizes, int n_in,
                              void* d_out, int out_size) {
    const float* x      = (const float*)d_in[0];
    const unsigned char* mask_raw = (const unsigned char*)d_in[1];
    const float* qkv_w  = (const float*)d_in[2];
    const float* q_bias = (const float*)d_in[3];
    const float* v_bias = (const float*)d_in[4];
    const float* proj_w = (const float*)d_in[5];
    const float* proj_b = (const float*)d_in[6];
    float* out          = (float*)d_out;
    (void)in_sizes; (void)n_in; (void)out_size;

    cudaFuncSetAttribute(attn_kernel,
                         cudaFuncAttributeMaxDynamicSharedMemorySize, ATTN_SMEM_BYTES);
    cudaFuncSetAttribute(mma_gemm_kernel<0>,
                         cudaFuncAttributeMaxDynamicSharedMemorySize, GEMM_DSMEM);
    cudaFuncSetAttribute(mma_gemm_kernel<1>,
                         cudaFuncAttributeMaxDynamicSharedMemorySize, GEMM_DSMEM);

    float* attn_ptr = nullptr;
    __nv_bfloat16 *xs = nullptr, *ws = nullptr, *as = nullptr, *ps = nullptr;
    cudaGetSymbolAddress((void**)&attn_ptr, g_attn);
    cudaGetSymbolAddress((void**)&xs, g_xs);
    cudaGetSymbolAddress((void**)&ws, g_ws);
    cudaGetSymbolAddress((void**)&as, g_as);
    cudaGetSymbolAddress((void**)&ps, g_ps);

    // 1) mask
    mask_canon_kernel<<<1, 256>>>(mask_raw);

    // 2) split conversions for QKV GEMM
    {
        int tA = MTOT * DIM;
        split_kernel<0><<<(tA + 255) / 256, 256>>>(x, xs, tA);
        int tB = 3 * DIM * DIM;
        split_kernel<1><<<(tB + 255) / 256, 256>>>(qkv_w, ws, tB);
    }

    // 3) QKV GEMM (scatter epilogue): [8192 x 2304]
    mma_gemm_kernel<1><<<dim3(3 * DIM / 128, MTOT / 128), 256, GEMM_DSMEM>>>(
        xs, ws, q_bias, v_bias, nullptr, 3 * DIM);

    // 4) attention
    attn_kernel<<<dim3(NN_ / 64, BB * NHEAD), 256, ATTN_SMEM_BYTES>>>();

    // 5) split conversions for projection
    {
        int tA = MTOT * DIM;
        split_kernel<0><<<(tA + 255) / 256, 256>>>(attn_ptr, as, tA);
        int tB = DIM * DIM;
        split_kernel<1><<<(tB + 255) / 256, 256>>>(proj_w, ps, tB);
    }

    // 6) projection GEMM: [8192 x 768]
    mma_gemm_kernel<0><<<dim3(DIM / 128, MTOT / 128), 256, GEMM_DSMEM>>>(
        as, ps, nullptr, proj_b, out, DIM);
}

// round 5
// speedup vs baseline: 2.8485x; 1.8958x over previous
#include <cuda_runtime.h>
#include <cuda_bf16.h>
#include <cstdint>

// ---------------------------------------------------------------------------
// AttentionWithCAE: y = proj( attn( x@qkv_w.T + [q_bias,0,v_bias] ) )
// B=8, N=1024, C=768, H=12, hd=64, SCALE=0.125
// Everything on mma.sync bf16 (split hi/lo 3-term, fp32 accumulate).
// ---------------------------------------------------------------------------

#define DIM   768
#define NHEAD 12
#define HD    64
#define BB    8
#define NN_   1024
#define MTOT  (BB * NN_)          // 8192
#define QKSCALE 0.125f
#define K2    (3 * DIM)           // 2304 expanded K
#define NC64  (K2 / 64)           // 36 K-chunks of 64
#define BHTOT (BB * NHEAD)        // 96

// scratch (device globals; no allocations allowed)
__device__ unsigned char g_mask[BB * NN_];
__device__ __nv_bfloat16 g_xs[MTOT * K2];        // x split     [Ah,Ah,Al]
__device__ __nv_bfloat16 g_ws[3 * DIM * K2];     // qkv_w split [Bh,Bl,Bh]
__device__ __nv_bfloat16 g_as[MTOT * K2];        // attn out split [hi,hi,lo]
__device__ __nv_bfloat16 g_ps[DIM * K2];         // proj_w split

// q/k/v bf16 hi/lo planes, layout [bh][n][64]
__device__ __nv_bfloat16 g_qh[BHTOT * NN_ * HD];
__device__ __nv_bfloat16 g_ql[BHTOT * NN_ * HD];
__device__ __nv_bfloat16 g_kh[BHTOT * NN_ * HD];
__device__ __nv_bfloat16 g_kl[BHTOT * NN_ * HD];
__device__ __nv_bfloat16 g_vh[BHTOT * NN_ * HD];
__device__ __nv_bfloat16 g_vl[BHTOT * NN_ * HD];

// ---------------------------------------------------------------------------
// helpers
// ---------------------------------------------------------------------------
__device__ __forceinline__ uint32_t smem_u32(const void* p) {
    uint32_t a;
    asm("{ .reg .u64 t; cvta.to.shared.u64 t, %1; cvt.u32.u64 %0, t; }"
        : "=r"(a) : "l"(p));
    return a;
}
#define SW128(o) ((o) ^ (((o) >> 3) & 0x70))

#define CP_ASYNC16(dst, src) \
    asm volatile("cp.async.cg.shared.global [%0], [%1], 16;" \
                 :: "r"(dst), "l"(src) : "memory")
#define CP_COMMIT() asm volatile("cp.async.commit_group;" ::: "memory")
#define CP_WAIT0()  asm volatile("cp.async.wait_group 0;" ::: "memory")
#define CP_WAIT1()  asm volatile("cp.async.wait_group 1;" ::: "memory")

__device__ __forceinline__ void ldsm4(uint32_t* r, uint32_t addr) {
    asm volatile("ldmatrix.sync.aligned.m8n8.x4.shared.b16 {%0,%1,%2,%3}, [%4];"
        : "=r"(r[0]), "=r"(r[1]), "=r"(r[2]), "=r"(r[3]) : "r"(addr));
}
__device__ __forceinline__ void ldsm4t(uint32_t* r, uint32_t addr) {
    asm volatile("ldmatrix.sync.aligned.m8n8.x4.trans.shared.b16 {%0,%1,%2,%3}, [%4];"
        : "=r"(r[0]), "=r"(r[1]), "=r"(r[2]), "=r"(r[3]) : "r"(addr));
}
__device__ __forceinline__ void mma16816(float* d, const uint32_t* a,
                                         const uint32_t* b) {
    asm volatile(
        "mma.sync.aligned.m16n8k16.row.col.f32.bf16.bf16.f32 "
        "{%0,%1,%2,%3}, {%4,%5,%6,%7}, {%8,%9}, {%0,%1,%2,%3};"
        : "+f"(d[0]), "+f"(d[1]), "+f"(d[2]), "+f"(d[3])
        : "r"(a[0]), "r"(a[1]), "r"(a[2]), "r"(a[3]), "r"(b[0]), "r"(b[1]));
}
__device__ __forceinline__ uint32_t packbf(float x, float y) {
    __nv_bfloat162 t = __floats2bfloat162_rn(x, y);
    return *(uint32_t*)&t;
}

// ---------------------------------------------------------------------------
// mask canonicalization (handles bool/int32/f32 payloads)
// ---------------------------------------------------------------------------
__global__ void mask_canon_kernel(const unsigned char* __restrict__ raw) {
    __shared__ int s_mis, s_notf, s_one;
    if (threadIdx.x == 0) { s_mis = 0; s_notf = 0; s_one = 0; }
    __syncthreads();
    int mis = 0, notf = 0, one = 0;
    const int* ri = (const int*)raw;
    for (int i = threadIdx.x; i < MTOT; i += blockDim.x)
        if ((i & 3) != 0 && raw[i] != 0) mis = 1;
    for (int i = threadIdx.x; i < MTOT / 4; i += blockDim.x) {
        int v = ri[i];
        if (v == 0x3f800000) one = 1; else if (v != 0) notf = 1;
    }
    if (mis)  atomicOr(&s_mis, 1);
    if (notf) atomicOr(&s_notf, 1);
    if (one)  atomicOr(&s_one, 1);
    __syncthreads();
    int is_f32 = (!s_notf) && s_one;
    int is_i32 = (!is_f32) && (!s_mis);
    for (int i = threadIdx.x; i < MTOT; i += blockDim.x) {
        unsigned char m;
        if (is_f32)      m = (((const float*)raw)[i] != 0.0f) ? 1 : 0;
        else if (is_i32) m = (((const int*)raw)[i]   != 0)    ? 1 : 0;
        else             m = (raw[i] != 0) ? 1 : 0;
        g_mask[i] = m;
    }
}

// ---------------------------------------------------------------------------
// split conversion: src[rows][768] f32 -> dst[rows][2304] bf16
// pattern 0 (A side): [hi, hi, lo] ; pattern 1 (B side): [hi, lo, hi]
// ---------------------------------------------------------------------------
template <int PAT>
__global__ void split_kernel(const float* __restrict__ src,
                             __nv_bfloat16* __restrict__ dst, int total) {
    int i = blockIdx.x * blockDim.x + threadIdx.x;
    if (i >= total) return;
    int m = i / DIM, k = i % DIM;
    float v = src[i];
    __nv_bfloat16 h = __float2bfloat16(v);
    __nv_bfloat16 l = __float2bfloat16(v - __bfloat162float(h));
    size_t base = (size_t)m * K2 + k;
    if (PAT == 0) { dst[base] = h; dst[base + DIM] = h; dst[base + 2 * DIM] = l; }
    else          { dst[base] = h; dst[base + DIM] = l; dst[base + 2 * DIM] = h; }
}

// ---------------------------------------------------------------------------
// mma.sync GEMM: C[M, Ntot] = A'[M,2304] @ B'[Ntot,2304]^T
// MODE 0: out = C + bias_b[n]                         (projection)
// MODE 1: split-scatter to q/k/v hi-lo planes (+biases, q*scale)
// ---------------------------------------------------------------------------
#define TILE16K  16384
#define STAGE_B  (2 * TILE16K)
#define GEMM_DSMEM (2 * STAGE_B)       // 65536

template <int MODE>
__global__ __launch_bounds__(256, 1) void mma_gemm_kernel(
    const __nv_bfloat16* __restrict__ A2, const __nv_bfloat16* __restrict__ B2,
    const float* __restrict__ bias_a, const float* __restrict__ bias_b,
    float* __restrict__ out, int Ntot)
{
    extern __shared__ char sm[];
    const int tid  = threadIdx.x;
    const int lane = tid & 31;
    const int wid  = tid >> 5;
    const int wm   = wid & 3;
    const int wn   = wid >> 2;
    const int m0 = blockIdx.y * 128;
    const int n0 = blockIdx.x * 128;

    float acc[2][8][4];
#pragma unroll
    for (int a = 0; a < 2; a++)
#pragma unroll
        for (int b = 0; b < 8; b++)
#pragma unroll
            for (int c = 0; c < 4; c++) acc[a][b][c] = 0.f;

    auto load_tiles = [&](int kt, int s) {
        char* sa = sm + s * STAGE_B;
        char* sb = sa + TILE16K;
        const int k0 = kt * 64;
#pragma unroll
        for (int i = 0; i < 4; i++) {
            int idx = i * 256 + tid;
            int r = idx >> 3, ch = idx & 7;
            uint32_t dst = smem_u32(sa + SW128((uint32_t)(r * 128 + ch * 16)));
            CP_ASYNC16(dst, A2 + (size_t)(m0 + r) * K2 + k0 + ch * 8);
        }
#pragma unroll
        for (int i = 0; i < 4; i++) {
            int idx = i * 256 + tid;
            int r = idx >> 3, ch = idx & 7;
            uint32_t dst = smem_u32(sb + SW128((uint32_t)(r * 128 + ch * 16)));
            CP_ASYNC16(dst, B2 + (size_t)(n0 + r) * K2 + k0 + ch * 8);
        }
    };

    load_tiles(0, 0);
    CP_COMMIT();

    for (int kt = 0; kt < NC64; kt++) {
        const int s = kt & 1;
        if (kt + 1 < NC64) {
            load_tiles(kt + 1, s ^ 1);
            CP_COMMIT();
            CP_WAIT1();
        } else {
            CP_WAIT0();
        }
        __syncthreads();

        const uint32_t a_base = smem_u32(sm + s * STAGE_B);
        const uint32_t b_base = a_base + TILE16K;
#pragma unroll
        for (int ks = 0; ks < 4; ks++) {
            uint32_t afr[2][4];
#pragma unroll
            for (int mt = 0; mt < 2; mt++) {
                int row = wm * 32 + mt * 16 + (lane & 15);
                uint32_t off = SW128((uint32_t)(row * 128 + ks * 32
                                                + ((lane >> 4) << 4)));
                ldsm4(afr[mt], a_base + off);
            }
            uint32_t bfr[4][4];
#pragma unroll
            for (int p = 0; p < 4; p++) {
                int row = wn * 64 + p * 16 + ((lane >> 4) << 3) + (lane & 7);
                uint32_t off = SW128((uint32_t)(row * 128 + ks * 32
                                                + (((lane >> 3) & 1) << 4)));
                ldsm4(bfr[p], b_base + off);
            }
#pragma unroll
            for (int mt = 0; mt < 2; mt++)
#pragma unroll
                for (int p = 0; p < 4; p++) {
                    mma16816(acc[mt][2 * p + 0], afr[mt], &bfr[p][0]);
                    mma16816(acc[mt][2 * p + 1], afr[mt], &bfr[p][2]);
                }
        }
        __syncthreads();
    }

    // epilogue straight from registers
#pragma unroll
    for (int mt = 0; mt < 2; mt++) {
#pragma unroll
        for (int nt = 0; nt < 8; nt++) {
            int rb = m0 + wm * 32 + mt * 16 + (lane >> 2);
            int cb = n0 + wn * 64 + nt * 8 + ((lane & 3) << 1);
#pragma unroll
            for (int h2 = 0; h2 < 2; h2++) {
                int m = rb + h2 * 8;
                float v0 = acc[mt][nt][h2 * 2 + 0];
                float v1 = acc[mt][nt][h2 * 2 + 1];
                if (MODE == 0) {
                    float2 o = make_float2(v0 + bias_b[cb], v1 + bias_b[cb + 1]);
                    *(float2*)&out[(size_t)m * Ntot + cb] = o;
                } else {
                    int which = cb / DIM;
                    int cc = cb - which * DIM;
                    int h = cc >> 6, d = cc & 63;
                    int b = m >> 10, nn = m & 1023;
                    size_t dst = ((size_t)(b * NHEAD + h) * NN_ + nn) * HD + d;
                    if (which == 0) { v0 = (v0 + bias_a[cc]) * QKSCALE;
                                      v1 = (v1 + bias_a[cc + 1]) * QKSCALE; }
                    else if (which == 2) { v0 += bias_b[cc]; v1 += bias_b[cc + 1]; }
                    __nv_bfloat16 h0 = __float2bfloat16(v0);
                    __nv_bfloat16 h1 = __float2bfloat16(v1);
                    uint32_t lop = packbf(v0 - __bfloat162float(h0),
                                          v1 - __bfloat162float(h1));
                    uint32_t hp; { __nv_bfloat162 t; t.x = h0; t.y = h1;
                                   hp = *(uint32_t*)&t; }
                    __nv_bfloat16* ph; __nv_bfloat16* pl;
                    if (which == 0)      { ph = g_qh; pl = g_ql; }
                    else if (which == 1) { ph = g_kh; pl = g_kl; }
                    else                 { ph = g_vh; pl = g_vl; }
                    *(uint32_t*)&ph[dst] = hp;
                    *(uint32_t*)&pl[dst] = lop;
                }
            }
        }
    }
}

// ---------------------------------------------------------------------------
// Tensor-core flash attention.
// CTA: 64 q-rows x 1 head, 4 warps (16 rows each). Key tile = 64.
// S = Qh*Kh + Qh*Kl + Ql*Kh ; P split hi/lo ; O += Ph*Vh + Ph*Vl + Pl*Vh.
// smem: 2 stages x {Kh,Kl,Vh,Vl}[64][128B swizzled] = 65536 B dynamic.
// ---------------------------------------------------------------------------
#define KT 64
#define NKT (NN_ / KT)             // 16
#define ASTAGE 32768
#define ATTN_DSMEM (2 * ASTAGE)

__global__ __launch_bounds__(128) void attn_mma_kernel() {
    extern __shared__ char sm[];
    __shared__ float Ms[2][KT];

    const int tid  = threadIdx.x;
    const int lane = tid & 31;
    const int warp = tid >> 5;
    const int q0 = blockIdx.x * 64;
    const int bh = blockIdx.y;
    const int b  = bh / NHEAD;
    const size_t hbase = (size_t)bh * NN_ * HD;

    const __nv_bfloat16* qh_g = g_qh + hbase;
    const __nv_bfloat16* ql_g = g_ql + hbase;
    const __nv_bfloat16* kh_g = g_kh + hbase;
    const __nv_bfloat16* kl_g = g_kl + hbase;
    const __nv_bfloat16* vh_g = g_vh + hbase;
    const __nv_bfloat16* vl_g = g_vl + hbase;

    // ---- stage Q (hi,lo) through smem, ldmatrix to registers ----
#pragma unroll
    for (int i = 0; i < 8; i++) {
        int idx = i * 128 + tid;               // 0..1023
        int arr = idx >> 9;                    // 0 hi, 1 lo
        int r = (idx >> 3) & 63, c = idx & 7;
        const __nv_bfloat16* src = (arr ? ql_g : qh_g) + (size_t)(q0 + r) * HD + c * 8;
        uint32_t dst = smem_u32(sm + arr * 8192 + SW128((uint32_t)(r * 128 + c * 16)));
        CP_ASYNC16(dst, src);
    }
    CP_COMMIT(); CP_WAIT0();
    __syncthreads();

    uint32_t qfh[4][4], qfl[4][4];
#pragma unroll
    for (int s = 0; s < 4; s++) {
        int row = warp * 16 + (lane & 15);
        uint32_t off = SW128((uint32_t)(row * 128 + s * 32 + ((lane >> 4) << 4)));
        ldsm4(qfh[s], smem_u32(sm) + off);
        ldsm4(qfl[s], smem_u32(sm) + 8192 + off);
    }
    __syncthreads();

    auto load_kv = [&](int t, int s) {
        int k0 = t * KT;
        char* st = sm + s * ASTAGE;
#pragma unroll
        for (int i = 0; i < 16; i++) {
            int idx = i * 128 + tid;           // 0..2047
            int arr = idx >> 9;                // 0 kh, 1 kl, 2 vh, 3 vl
            int r = (idx >> 3) & 63, c = idx & 7;
            const __nv_bfloat16* bsrc =
                (arr == 0) ? kh_g : (arr == 1) ? kl_g : (arr == 2) ? vh_g : vl_g;
            uint32_t dst = smem_u32(st + arr * 8192 + SW128((uint32_t)(r * 128 + c * 16)));
            CP_ASYNC16(dst, bsrc + (size_t)(k0 + r) * HD + c * 8);
        }
        if (tid < KT)
            Ms[s][tid] = g_mask[b * NN_ + k0 + tid] ? -1e30f : 0.f;
    };

    float m_[2] = {-1e30f, -1e30f};
    float l_[2] = {0.f, 0.f};
    float Oa[8][4];
#pragma unroll
    for (int j = 0; j < 8; j++)
#pragma unroll
        for (int c = 0; c < 4; c++) Oa[j][c] = 0.f;

    load_kv(0, 0);
    CP_COMMIT();

    for (int t = 0; t < NKT; t++) {
        const int s = t & 1;
        if (t + 1 < NKT) { load_kv(t + 1, s ^ 1); CP_COMMIT(); CP_WAIT1(); }
        else             { CP_WAIT0(); }
        __syncthreads();

        const uint32_t kh_b = smem_u32(sm + s * ASTAGE);
        const uint32_t kl_b = kh_b + 8192;
        const uint32_t vh_b = kh_b + 16384;
        const uint32_t vl_b = kh_b + 24576;

        // ---- S = Q K^T (3-term) ----
        float Sa[8][4];
#pragma unroll
        for (int j = 0; j < 8; j++)
#pragma unroll
            for (int c = 0; c < 4; c++) Sa[j][c] = 0.f;

#pragma unroll
        for (int sk = 0; sk < 4; sk++) {
            uint32_t bhf[4][4], blf[4][4];
#pragma unroll
            for (int p = 0; p < 4; p++) {
                int row = p * 16 + ((lane >> 4) << 3) + (lane & 7);
                uint32_t off = SW128((uint32_t)(row * 128 + sk * 32
                                                + (((lane >> 3) & 1) << 4)));
                ldsm4(bhf[p], kh_b + off);
                ldsm4(blf[p], kl_b + off);
            }
#pragma unroll
            for (int p = 0; p < 4; p++) {
                mma16816(Sa[2 * p + 0], qfh[sk], &bhf[p][0]);
                mma16816(Sa[2 * p + 1], qfh[sk], &bhf[p][2]);
                mma16816(Sa[2 * p + 0], qfh[sk], &blf[p][0]);
                mma16816(Sa[2 * p + 1], qfh[sk], &blf[p][2]);
                mma16816(Sa[2 * p + 0], qfl[sk], &bhf[p][0]);
                mma16816(Sa[2 * p + 1], qfl[sk], &bhf[p][2]);
            }
        }

        // ---- mask + online softmax ----
        const int cb = (lane & 3) << 1;
#pragma unroll
        for (int j = 0; j < 8; j++) {
            float2 ma = *(float2*)&Ms[s][j * 8 + cb];
            Sa[j][0] += ma.x; Sa[j][1] += ma.y;
            Sa[j][2] += ma.x; Sa[j][3] += ma.y;
        }
#pragma unroll
        for (int h = 0; h < 2; h++) {
            float mx = -1e30f;
#pragma unroll
            for (int j = 0; j < 8; j++)
                mx = fmaxf(mx, fmaxf(Sa[j][2 * h], Sa[j][2 * h + 1]));
            mx = fmaxf(mx, __shfl_xor_sync(0xffffffffu, mx, 1));
            mx = fmaxf(mx, __shfl_xor_sync(0xffffffffu, mx, 2));
            float mn = fmaxf(m_[h], mx);
            float corr = __expf(m_[h] - mn);
            m_[h] = mn;
            float rs = 0.f;
#pragma unroll
            for (int j = 0; j < 8; j++) {
                Sa[j][2 * h]     = __expf(Sa[j][2 * h]     - mn);
                Sa[j][2 * h + 1] = __expf(Sa[j][2 * h + 1] - mn);
                rs += Sa[j][2 * h] + Sa[j][2 * h + 1];
            }
            rs += __shfl_xor_sync(0xffffffffu, rs, 1);
            rs += __shfl_xor_sync(0xffffffffu, rs, 2);
            l_[h] = l_[h] * corr + rs;
#pragma unroll
            for (int j = 0; j < 8; j++) {
                Oa[j][2 * h]     *= corr;
                Oa[j][2 * h + 1] *= corr;
            }
        }

        // ---- O += P V (3-term), P repacked from S fragments ----
#pragma unroll
        for (int k2 = 0; k2 < 4; k2++) {
            uint32_t pah[4], pal[4];
#pragma unroll
            for (int u = 0; u < 2; u++) {
                int j = 2 * k2 + u;
                float p0 = Sa[j][0], p1 = Sa[j][1];
                float p2 = Sa[j][2], p3 = Sa[j][3];
                __nv_bfloat16 h0 = __float2bfloat16(p0), h1 = __float2bfloat16(p1);
                __nv_bfloat16 h2 = __float2bfloat16(p2), h3 = __float2bfloat16(p3);
                __nv_bfloat162 t0; t0.x = h0; t0.y = h1;
                __nv_bfloat162 t1; t1.x = h2; t1.y = h3;
                pah[u]     = *(uint32_t*)&t0;
                pah[u + 2] = *(uint32_t*)&t1;
                pal[u]     = packbf(p0 - __bfloat162float(h0),
                                    p1 - __bfloat162float(h1));
                pal[u + 2] = packbf(p2 - __bfloat162float(h2),
                                    p3 - __bfloat162float(h3));
            }
            // reorder to mma A-frag: {m0-7 k0-7, m8-15 k0-7, m0-7 k8-15, m8-15 k8-15}
            uint32_t pahf[4] = {pah[0], pah[2], pah[1], pah[3]};
            uint32_t palf[4] = {pal[0], pal[2], pal[1], pal[3]};
            uint32_t bvh[4][4], bvl[4][4];
#pragma unroll
            for (int p = 0; p < 4; p++) {
                int row = k2 * 16 + (lane & 15);
                uint32_t off = SW128((uint32_t)(row * 128 + p * 32
                                                + ((lane >> 4) << 4)));
                ldsm4t(bvh[p], vh_b + off);
                ldsm4t(bvl[p], vl_b + off);
            }
#pragma unroll
            for (int p = 0; p < 4; p++) {
                mma16816(Oa[2 * p + 0], pahf, &bvh[p][0]);
                mma16816(Oa[2 * p + 1], pahf, &bvh[p][2]);
                mma16816(Oa[2 * p + 0], pahf, &bvl[p][0]);
                mma16816(Oa[2 * p + 1], pahf, &bvl[p][2]);
                mma16816(Oa[2 * p + 0], palf, &bvh[p][0]);
                mma16816(Oa[2 * p + 1], palf, &bvh[p][2]);
            }
        }
        __syncthreads();
    }

    // ---- epilogue: normalize, split, write g_as ([hi,hi,lo] @ k,768+k,1536+k)
    const int hcol = (bh % NHEAD) * HD;
#pragma unroll
    for (int h = 0; h < 2; h++) {
        float inv = 1.f / l_[h];
        int row = q0 + warp * 16 + (lane >> 2) + h * 8;
        size_t mrow = (size_t)(b * NN_ + row) * K2;
#pragma unroll
        for (int j = 0; j < 8; j++) {
            int col = hcol + j * 8 + ((lane & 3) << 1);
            float v0 = Oa[j][2 * h] * inv;
            float v1 = Oa[j][2 * h + 1] * inv;
            __nv_bfloat16 h0 = __float2bfloat16(v0);
            __nv_bfloat16 h1 = __float2bfloat16(v1);
            __nv_bfloat162 hp; hp.x = h0; hp.y = h1;
            uint32_t lop = packbf(v0 - __bfloat162float(h0),
                                  v1 - __bfloat162float(h1));
            *(uint32_t*)&g_as[mrow + col]            = *(uint32_t*)&hp;
            *(uint32_t*)&g_as[mrow + DIM + col]      = *(uint32_t*)&hp;
            *(uint32_t*)&g_as[mrow + 2 * DIM + col]  = lop;
        }
    }
}

// ---------------------------------------------------------------------------
// launch
// ---------------------------------------------------------------------------
extern "C" void kernel_launch(void* const* d_in, const int* in_sizes, int n_in,
                              void* d_out, int out_size) {
    const float* x      = (const float*)d_in[0];
    const unsigned char* mask_raw = (const unsigned char*)d_in[1];
    const float* qkv_w  = (const float*)d_in[2];
    const float* q_bias = (const float*)d_in[3];
    const float* v_bias = (const float*)d_in[4];
    const float* proj_w = (const float*)d_in[5];
    const float* proj_b = (const float*)d_in[6];
    float* out          = (float*)d_out;
    (void)in_sizes; (void)n_in; (void)out_size;

    cudaFuncSetAttribute(mma_gemm_kernel<0>,
                         cudaFuncAttributeMaxDynamicSharedMemorySize, GEMM_DSMEM);
    cudaFuncSetAttribute(mma_gemm_kernel<1>,
                         cudaFuncAttributeMaxDynamicSharedMemorySize, GEMM_DSMEM);
    cudaFuncSetAttribute(attn_mma_kernel,
                         cudaFuncAttributeMaxDynamicSharedMemorySize, ATTN_DSMEM);

    __nv_bfloat16 *xs = nullptr, *ws = nullptr, *as = nullptr, *ps = nullptr;
    cudaGetSymbolAddress((void**)&xs, g_xs);
    cudaGetSymbolAddress((void**)&ws, g_ws);
    cudaGetSymbolAddress((void**)&as, g_as);
    cudaGetSymbolAddress((void**)&ps, g_ps);

    // 1) mask
    mask_canon_kernel<<<1, 256>>>(mask_raw);

    // 2) split conversions (x, qkv_w, proj_w)
    {
        int tA = MTOT * DIM;
        split_kernel<0><<<(tA + 255) / 256, 256>>>(x, xs, tA);
        int tB = 3 * DIM * DIM;
        split_kernel<1><<<(tB + 255) / 256, 256>>>(qkv_w, ws, tB);
        int tP = DIM * DIM;
        split_kernel<1><<<(tP + 255) / 256, 256>>>(proj_w, ps, tP);
    }

    // 3) QKV GEMM -> q/k/v bf16 hi-lo planes
    mma_gemm_kernel<1><<<dim3(3 * DIM / 128, MTOT / 128), 256, GEMM_DSMEM>>>(
        xs, ws, q_bias, v_bias, nullptr, 3 * DIM);

    // 4) tensor-core attention -> g_as (pre-split proj input)
    attn_mma_kernel<<<dim3(NN_ / 64, BHTOT), 128, ATTN_DSMEM>>>();

    // 5) projection GEMM: [8192 x 768]
    mma_gemm_kernel<0><<<dim3(DIM / 128, MTOT / 128), 256, GEMM_DSMEM>>>(
        as, ps, nullptr, proj_b, out, DIM);
}